// round 7
// baseline (speedup 1.0000x reference)
#include <cuda_runtime.h>
#include <cuda_bf16.h>
#include <cstdint>

#define NB 8192
#define ND 512
#define BMr 128
#define BNr 256
#define BK 32
#define NK (ND / BK)          // 16
#define NTN (NB / BNr)        // 32
#define NBLK 1056             // sum_{bi=0}^{63} (32 - bi/2)
#define SST 40                // bf16 elems per smem row
#define ROWB (SST * 2)        // 80 bytes

#define ASTAGE (BMr * ROWB)   // 10240
#define BSTAGE (BNr * ROWB)   // 20480
#define OFF_A 0
#define OFF_B (3 * ASTAGE)             // 30720
#define OFF_EPI (OFF_B + 3 * BSTAGE)   // 92160
#define OFF_INVA (OFF_EPI)
#define OFF_SQA  (OFF_INVA + 512)
#define OFF_INVB (OFF_SQA + 512)
#define OFF_SQB  (OFF_INVB + 1024)
#define OFF_YA   (OFF_SQB + 1024)
#define OFF_YB   (OFF_YA + 1024)
#define OFF_RED  (OFF_YB + 2048)
#define SMEM_TOTAL (OFF_RED + 64)      // 98368

__device__ float g_inv[NB];
__device__ float g_sq[NB];
__device__ float g_acc;
__device__ __nv_bfloat16 g_xbf[(size_t)NB * ND];

__device__ __forceinline__ uint32_t smem_to_u32(const void* p) {
    uint32_t a;
    asm("{ .reg .u64 t; cvta.to.shared.u64 t, %1; cvt.u32.u64 %0, t; }" : "=r"(a) : "l"(p));
    return a;
}
__device__ __forceinline__ void cp_async16(uint32_t saddr, const void* gaddr) {
    asm volatile("cp.async.cg.shared.global [%0], [%1], 16;" :: "r"(saddr), "l"(gaddr) : "memory");
}
__device__ __forceinline__ void ldmx4(uint32_t* r, uint32_t addr) {
    asm volatile("ldmatrix.sync.aligned.m8n8.x4.shared.b16 {%0,%1,%2,%3}, [%4];"
                 : "=r"(r[0]), "=r"(r[1]), "=r"(r[2]), "=r"(r[3]) : "r"(addr));
}
__device__ __forceinline__ void mma16816(float* c, const uint32_t* a, uint32_t b0, uint32_t b1) {
    asm volatile(
        "mma.sync.aligned.m16n8k16.row.col.f32.bf16.bf16.f32 "
        "{%0,%1,%2,%3}, {%4,%5,%6,%7}, {%8,%9}, {%0,%1,%2,%3};"
        : "+f"(c[0]), "+f"(c[1]), "+f"(c[2]), "+f"(c[3])
        : "r"(a[0]), "r"(a[1]), "r"(a[2]), "r"(a[3]), "r"(b0), "r"(b1));
}

// ---------------------------------------------------------------------------
// Kernel 1: fused norms + fp32->bf16 conversion. One warp per row.
// ---------------------------------------------------------------------------
__global__ __launch_bounds__(256) void prep_convert(const float* __restrict__ x) {
    int row = blockIdx.x * 8 + (threadIdx.x >> 5);
    int lane = threadIdx.x & 31;
    const float4* xr = (const float4*)(x + (size_t)row * ND) + lane * 4;
    float4 v[4];
    v[0] = xr[0]; v[1] = xr[1]; v[2] = xr[2]; v[3] = xr[3];

    float s = 0.f;
    #pragma unroll
    for (int i = 0; i < 4; i++)
        s += v[i].x * v[i].x + v[i].y * v[i].y + v[i].z * v[i].z + v[i].w * v[i].w;
    #pragma unroll
    for (int o = 16; o; o >>= 1) s += __shfl_xor_sync(0xffffffffu, s, o);

    float inv = 1.0f / sqrtf(s);

    float sq = 0.f;
    #pragma unroll
    for (int i = 0; i < 4; i++) {
        float a = v[i].x * inv, b = v[i].y * inv, c = v[i].z * inv, d = v[i].w * inv;
        sq += a * a + b * b + c * c + d * d;
    }
    #pragma unroll
    for (int o = 16; o; o >>= 1) sq += __shfl_xor_sync(0xffffffffu, sq, o);

    if (lane == 0) {
        g_inv[row] = inv;
        g_sq[row] = sq;
        if (row == 0) g_acc = 0.f;
    }

    uint32_t u[8];
    #pragma unroll
    for (int i = 0; i < 4; i++) {
        __nv_bfloat162 p0 = __floats2bfloat162_rn(v[i].x, v[i].y);
        __nv_bfloat162 p1 = __floats2bfloat162_rn(v[i].z, v[i].w);
        u[2 * i]     = *reinterpret_cast<uint32_t*>(&p0);
        u[2 * i + 1] = *reinterpret_cast<uint32_t*>(&p1);
    }
    uint4* dst = (uint4*)(g_xbf + (size_t)row * ND + lane * 16);
    dst[0] = make_uint4(u[0], u[1], u[2], u[3]);
    dst[1] = make_uint4(u[4], u[5], u[6], u[7]);
}

// ---------------------------------------------------------------------------
// Kernel 2: 128x256 CTA tile, warp tile 64x64 (2x4 warps), 3-stage cp.async.
// Upper-triangle blocks only; fused loss epilogue on register accumulators.
// ---------------------------------------------------------------------------
__global__ __launch_bounds__(256, 1) void gemm_loss(const long long* __restrict__ y) {
    extern __shared__ char smem[];
    const uint32_t sb = smem_to_u32(smem);
    const int tid = threadIdx.x;
    const int lane = tid & 31;
    const int wid = tid >> 5;
    const int wm = wid & 1;      // 0..1 -> 64-row slab
    const int wn = wid >> 1;     // 0..3 -> 64-col slab

    // decode upper-triangle block (bi in 128-row units, bjj in 256-col units)
    int t = blockIdx.x, bi = 0;
    while (t >= NTN - (bi >> 1)) { t -= NTN - (bi >> 1); bi++; }
    const int bjj = (bi >> 1) + t;

    float* invA_s = (float*)(smem + OFF_INVA);
    float* sqA_s  = (float*)(smem + OFF_SQA);
    float* invB_s = (float*)(smem + OFF_INVB);
    float* sqB_s  = (float*)(smem + OFF_SQB);
    long long* yA_s = (long long*)(smem + OFF_YA);
    long long* yB_s = (long long*)(smem + OFF_YB);
    float* redr = (float*)(smem + OFF_RED);

    if (tid < BMr) {
        const int gi = bi * BMr + tid;
        invA_s[tid] = g_inv[gi]; sqA_s[tid] = g_sq[gi]; yA_s[tid] = y[gi];
    }
    {
        const int gj = bjj * BNr + tid;
        invB_s[tid] = g_inv[gj]; sqB_s[tid] = g_sq[gj]; yB_s[tid] = y[gj];
    }

    // global load mapping
    // A: 128 rows x 32 cols, 2 threads/row, 32B each
    const __nv_bfloat16* gA = g_xbf + (size_t)(bi * BMr + (tid >> 1)) * ND + (tid & 1) * 16;
    const uint32_t sAoff = (uint32_t)(tid >> 1) * ROWB + (tid & 1) * 32;
    // B: 256 rows x 32 cols, 1 thread/row, 64B each
    const __nv_bfloat16* gB = g_xbf + (size_t)(bjj * BNr + tid) * ND;
    const uint32_t sBoff = (uint32_t)tid * ROWB;

#define LOAD_STAGE(st, kk) do {                                               \
        const uint32_t _a = sb + OFF_A + (st) * ASTAGE + sAoff;               \
        const __nv_bfloat16* _ga = gA + (kk) * BK;                            \
        cp_async16(_a,      _ga);                                             \
        cp_async16(_a + 16, _ga + 8);                                         \
        const uint32_t _b = sb + OFF_B + (st) * BSTAGE + sBoff;               \
        const __nv_bfloat16* _gb = gB + (kk) * BK;                            \
        cp_async16(_b,      _gb);                                             \
        cp_async16(_b + 16, _gb + 8);                                         \
        cp_async16(_b + 32, _gb + 16);                                        \
        cp_async16(_b + 48, _gb + 24);                                        \
        asm volatile("cp.async.commit_group;" ::: "memory");                  \
    } while (0)

    // ldmatrix lane addressing
    const int lr = lane & 7, lg = lane >> 3;
    const uint32_t aoff = (uint32_t)(wm * 64 + lr + (lg & 1) * 8) * ROWB + (lg >> 1) * 16;
    const uint32_t boff = (uint32_t)(wn * 64 + lr + (lg >> 1) * 8) * ROWB + (lg & 1) * 16;

    float c[4][8][4];
    #pragma unroll
    for (int mt = 0; mt < 4; mt++)
        #pragma unroll
        for (int nt = 0; nt < 8; nt++)
            #pragma unroll
            for (int r = 0; r < 4; r++) c[mt][nt][r] = 0.f;

    LOAD_STAGE(0, 0);
    LOAD_STAGE(1, 1);

    int st = 0, ls = 2;
    #pragma unroll 1
    for (int k = 0; k < NK; k++) {
        if (k < NK - 1) asm volatile("cp.async.wait_group 1;" ::: "memory");
        else            asm volatile("cp.async.wait_group 0;" ::: "memory");
        __syncthreads();
        if (k + 2 < NK) {
            LOAD_STAGE(ls, k + 2);
            if (++ls == 3) ls = 0;
        }
        const uint32_t uA = sb + OFF_A + st * ASTAGE;
        const uint32_t uB = sb + OFF_B + st * BSTAGE;
        if (++st == 3) st = 0;

        #pragma unroll
        for (int ks = 0; ks < 2; ks++) {
            uint32_t af[4][4], bf[4][4];
            #pragma unroll
            for (int mt = 0; mt < 4; mt++)
                ldmx4(af[mt], uA + aoff + mt * 16 * ROWB + ks * 32);
            #pragma unroll
            for (int p = 0; p < 4; p++)
                ldmx4(bf[p], uB + boff + p * 16 * ROWB + ks * 32);
            #pragma unroll
            for (int mt = 0; mt < 4; mt++)
                #pragma unroll
                for (int nt = 0; nt < 8; nt++)
                    mma16816(c[mt][nt], af[mt], bf[nt >> 1][(nt & 1) * 2],
                             bf[nt >> 1][(nt & 1) * 2 + 1]);
        }
    }

    // ---- fused loss epilogue on register fragments ----
    const int quad = lane >> 2;    // 0..7
    const int qt = lane & 3;       // 0..3
    float local = 0.f;

    #pragma unroll
    for (int mt = 0; mt < 4; mt++) {
        #pragma unroll
        for (int r2 = 0; r2 < 2; r2++) {
            const int li = wm * 64 + mt * 16 + quad + r2 * 8;
            const int gi = bi * BMr + li;
            const float invi = invA_s[li], sqi = sqA_s[li];
            const long long yi = yA_s[li];
            #pragma unroll
            for (int nt = 0; nt < 8; nt++) {
                #pragma unroll
                for (int r1 = 0; r1 < 2; r1++) {
                    const int lj = wn * 64 + nt * 8 + 2 * qt + r1;
                    const int gj = bjj * BNr + lj;
                    if (gj >= gi) {
                        const float g = c[mt][nt][r2 * 2 + r1] * invi * invB_s[lj];
                        const float dist2 = sqi + sqB_s[lj] - 2.0f * g;
                        const float hinge = fmaxf(1.2f - dist2, 0.0f);
                        local += 0.3f + ((yi == yB_s[lj]) ? hinge : -hinge);
                    }
                }
            }
        }
    }

    #pragma unroll
    for (int o = 16; o; o >>= 1) local += __shfl_xor_sync(0xffffffffu, local, o);
    if (lane == 0) redr[wid] = local;
    __syncthreads();
    if (tid == 0) {
        float s = 0.f;
        #pragma unroll
        for (int i = 0; i < 8; i++) s += redr[i];
        atomicAdd(&g_acc, s);
    }
}

// ---------------------------------------------------------------------------
// Kernel 3: finalize
// ---------------------------------------------------------------------------
__global__ void finalize_kernel(float* out) {
    const double m = 1.0 / ((double)NB * (double)NB - (double)NB);
    out[0] = (float)((double)g_acc * m);
}

extern "C" void kernel_launch(void* const* d_in, const int* in_sizes, int n_in,
                              void* d_out, int out_size) {
    const float* x = (const float*)d_in[0];
    const long long* y = (const long long*)d_in[1];
    float* out = (float*)d_out;

    cudaFuncSetAttribute(gemm_loss, cudaFuncAttributeMaxDynamicSharedMemorySize, SMEM_TOTAL);

    prep_convert<<<NB / 8, 256>>>(x);
    gemm_loss<<<NBLK, 256, SMEM_TOTAL>>>(y);
    finalize_kernel<<<1, 1>>>(out);
}

// round 8
// speedup vs baseline: 1.1906x; 1.1906x over previous
#include <cuda_runtime.h>
#include <cuda_bf16.h>
#include <cstdint>

#define NB 8192
#define ND 512
#define BM 128
#define BK 32
#define NK (ND / BK)                     // 16
#define NTILE (NB / BM)                  // 64
#define NPAIR (NTILE * (NTILE + 1) / 2)  // 2080
#define SST 40                           // bf16 elems per smem row
#define ROWB (SST * 2)                   // 80 bytes
#define NSTAGE 4
#define STAGE (BM * ROWB)                // 10240

#define OFF_A 0
#define OFF_B (NSTAGE * STAGE)                 // 40960
#define OFF_EPI (OFF_B + NSTAGE * STAGE)       // 81920
#define OFF_INVA (OFF_EPI)
#define OFF_SQA  (OFF_INVA + 512)
#define OFF_INVB (OFF_SQA + 512)
#define OFF_SQB  (OFF_INVB + 512)
#define OFF_YA   (OFF_SQB + 512)
#define OFF_YB   (OFF_YA + 1024)
#define OFF_RED  (OFF_YB + 1024)
#define SMEM_TOTAL (OFF_RED + 64)              // ~86 KB

__device__ float g_inv[NB];
__device__ float g_sq[NB];
__device__ float g_acc;
__device__ __nv_bfloat16 g_xbf[(size_t)NB * ND];

__device__ __forceinline__ uint32_t smem_to_u32(const void* p) {
    uint32_t a;
    asm("{ .reg .u64 t; cvta.to.shared.u64 t, %1; cvt.u32.u64 %0, t; }" : "=r"(a) : "l"(p));
    return a;
}
__device__ __forceinline__ void cp_async16(uint32_t saddr, const void* gaddr) {
    asm volatile("cp.async.cg.shared.global [%0], [%1], 16;" :: "r"(saddr), "l"(gaddr) : "memory");
}
__device__ __forceinline__ void ldmx4(uint32_t* r, uint32_t addr) {
    asm volatile("ldmatrix.sync.aligned.m8n8.x4.shared.b16 {%0,%1,%2,%3}, [%4];"
                 : "=r"(r[0]), "=r"(r[1]), "=r"(r[2]), "=r"(r[3]) : "r"(addr));
}
__device__ __forceinline__ void mma16816(float* c, const uint32_t* a, uint32_t b0, uint32_t b1) {
    asm volatile(
        "mma.sync.aligned.m16n8k16.row.col.f32.bf16.bf16.f32 "
        "{%0,%1,%2,%3}, {%4,%5,%6,%7}, {%8,%9}, {%0,%1,%2,%3};"
        : "+f"(c[0]), "+f"(c[1]), "+f"(c[2]), "+f"(c[3])
        : "r"(a[0]), "r"(a[1]), "r"(a[2]), "r"(a[3]), "r"(b0), "r"(b1));
}

// ---------------------------------------------------------------------------
// Kernel 1: fused norms + fp32->bf16 conversion. One warp per row.
// ---------------------------------------------------------------------------
__global__ __launch_bounds__(256) void prep_convert(const float* __restrict__ x) {
    int row = blockIdx.x * 8 + (threadIdx.x >> 5);
    int lane = threadIdx.x & 31;
    const float4* xr = (const float4*)(x + (size_t)row * ND) + lane * 4;
    float4 v[4];
    v[0] = xr[0]; v[1] = xr[1]; v[2] = xr[2]; v[3] = xr[3];

    float s = 0.f;
    #pragma unroll
    for (int i = 0; i < 4; i++)
        s += v[i].x * v[i].x + v[i].y * v[i].y + v[i].z * v[i].z + v[i].w * v[i].w;
    #pragma unroll
    for (int o = 16; o; o >>= 1) s += __shfl_xor_sync(0xffffffffu, s, o);

    float inv = 1.0f / sqrtf(s);

    float sq = 0.f;
    #pragma unroll
    for (int i = 0; i < 4; i++) {
        float a = v[i].x * inv, b = v[i].y * inv, c = v[i].z * inv, d = v[i].w * inv;
        sq += a * a + b * b + c * c + d * d;
    }
    #pragma unroll
    for (int o = 16; o; o >>= 1) sq += __shfl_xor_sync(0xffffffffu, sq, o);

    if (lane == 0) {
        g_inv[row] = inv;
        g_sq[row] = sq;
        if (row == 0) g_acc = 0.f;
    }

    uint32_t u[8];
    #pragma unroll
    for (int i = 0; i < 4; i++) {
        __nv_bfloat162 p0 = __floats2bfloat162_rn(v[i].x, v[i].y);
        __nv_bfloat162 p1 = __floats2bfloat162_rn(v[i].z, v[i].w);
        u[2 * i]     = *reinterpret_cast<uint32_t*>(&p0);
        u[2 * i + 1] = *reinterpret_cast<uint32_t*>(&p1);
    }
    uint4* dst = (uint4*)(g_xbf + (size_t)row * ND + lane * 16);
    dst[0] = make_uint4(u[0], u[1], u[2], u[3]);
    dst[1] = make_uint4(u[4], u[5], u[6], u[7]);
}

// ---------------------------------------------------------------------------
// Kernel 2: 128x128 CTA tile, 8 warps (4Mx2N), warp tile 32x64.
// 4-stage cp.async ring, ONE __syncthreads per k-iter. Fused loss epilogue.
// ---------------------------------------------------------------------------
__global__ __launch_bounds__(256, 2) void gemm_loss(const long long* __restrict__ y) {
    extern __shared__ char smem[];
    const uint32_t sb = smem_to_u32(smem);
    const int tid = threadIdx.x;
    const int lane = tid & 31;
    const int wid = tid >> 5;
    const int wm = wid & 3;     // 0..3  -> 32-row slab
    const int wn = wid >> 2;    // 0..1  -> 64-col slab

    // decode upper-triangle pair (bi, bj)
    int t = blockIdx.x, bi = 0;
    while (t >= NTILE - bi) { t -= NTILE - bi; bi++; }
    const int bj = bi + t;

    float* invA_s = (float*)(smem + OFF_INVA);
    float* sqA_s  = (float*)(smem + OFF_SQA);
    float* invB_s = (float*)(smem + OFF_INVB);
    float* sqB_s  = (float*)(smem + OFF_SQB);
    long long* yA_s = (long long*)(smem + OFF_YA);
    long long* yB_s = (long long*)(smem + OFF_YB);
    float* redr = (float*)(smem + OFF_RED);

    if (tid < BM) {
        const int gi = bi * BM + tid, gj = bj * BM + tid;
        invA_s[tid] = g_inv[gi]; sqA_s[tid] = g_sq[gi]; yA_s[tid] = y[gi];
        invB_s[tid] = g_inv[gj]; sqB_s[tid] = g_sq[gj]; yB_s[tid] = y[gj];
    }

    // global load mapping: each thread owns 32B of one A row and one B row
    const int lrow = tid >> 1;
    const int lc0 = (tid & 1) * 2;   // 16B-chunk index 0 or 2
    const __nv_bfloat16* gA = g_xbf + (size_t)(bi * BM + lrow) * ND + lc0 * 8;
    const __nv_bfloat16* gB = g_xbf + (size_t)(bj * BM + lrow) * ND + lc0 * 8;
    const uint32_t soff = (uint32_t)lrow * ROWB + lc0 * 16;

#define LOAD_STAGE(st, kk) do {                                               \
        const uint32_t _a = sb + OFF_A + (st) * STAGE + soff;                 \
        const uint32_t _b = sb + OFF_B + (st) * STAGE + soff;                 \
        const __nv_bfloat16* _ga = gA + (kk) * BK;                            \
        const __nv_bfloat16* _gb = gB + (kk) * BK;                            \
        cp_async16(_a,      _ga);                                             \
        cp_async16(_a + 16, _ga + 8);                                         \
        cp_async16(_b,      _gb);                                             \
        cp_async16(_b + 16, _gb + 8);                                         \
        asm volatile("cp.async.commit_group;" ::: "memory");                  \
    } while (0)

    // ldmatrix lane addressing (same mapping as the proven R5 kernel)
    const int lr = lane & 7, lg = lane >> 3;
    const uint32_t aoff = (uint32_t)(wm * 32 + lr + (lg & 1) * 8) * ROWB + (lg >> 1) * 16;
    const uint32_t boff = (uint32_t)(wn * 64 + lr + (lg >> 1) * 8) * ROWB + (lg & 1) * 16;

    float c[2][8][4];
    #pragma unroll
    for (int mt = 0; mt < 2; mt++)
        #pragma unroll
        for (int nt = 0; nt < 8; nt++)
            #pragma unroll
            for (int r = 0; r < 4; r++) c[mt][nt][r] = 0.f;

    LOAD_STAGE(0, 0);
    LOAD_STAGE(1, 1);
    LOAD_STAGE(2, 2);

    int st = 0, ls = 3;
    #pragma unroll 1
    for (int k = 0; k < NK; k++) {
        // wait until stage st's group has landed (exact tail handling)
        if (k < NK - 2)      asm volatile("cp.async.wait_group 2;" ::: "memory");
        else if (k == NK - 2) asm volatile("cp.async.wait_group 1;" ::: "memory");
        else                  asm volatile("cp.async.wait_group 0;" ::: "memory");
        __syncthreads();   // single barrier per iter: fences prior compute too

        if (k + 3 < NK) {
            LOAD_STAGE(ls, k + 3);
            if (++ls == NSTAGE) ls = 0;
        }

        const uint32_t uA = sb + OFF_A + st * STAGE;
        const uint32_t uB = sb + OFF_B + st * STAGE;
        if (++st == NSTAGE) st = 0;

        #pragma unroll
        for (int ks = 0; ks < 2; ks++) {
            uint32_t af[2][4], bf[4][4];
            #pragma unroll
            for (int mt = 0; mt < 2; mt++)
                ldmx4(af[mt], uA + aoff + mt * 16 * ROWB + ks * 32);
            #pragma unroll
            for (int p = 0; p < 4; p++)
                ldmx4(bf[p], uB + boff + p * 16 * ROWB + ks * 32);
            #pragma unroll
            for (int mt = 0; mt < 2; mt++)
                #pragma unroll
                for (int nt = 0; nt < 8; nt++)
                    mma16816(c[mt][nt], af[mt], bf[nt >> 1][(nt & 1) * 2],
                             bf[nt >> 1][(nt & 1) * 2 + 1]);
        }
    }

    // ---- fused loss epilogue on register fragments ----
    const int quad = lane >> 2;    // 0..7
    const int qt = lane & 3;       // 0..3
    float local = 0.f;

    #pragma unroll
    for (int mt = 0; mt < 2; mt++) {
        #pragma unroll
        for (int r2 = 0; r2 < 2; r2++) {
            const int li = wm * 32 + mt * 16 + quad + r2 * 8;
            const int gi = bi * BM + li;
            const float invi = invA_s[li], sqi = sqA_s[li];
            const long long yi = yA_s[li];
            #pragma unroll
            for (int nt = 0; nt < 8; nt++) {
                #pragma unroll
                for (int r1 = 0; r1 < 2; r1++) {
                    const int lj = wn * 64 + nt * 8 + 2 * qt + r1;
                    const int gj = bj * BM + lj;
                    if (gj >= gi) {
                        const float g = c[mt][nt][r2 * 2 + r1] * invi * invB_s[lj];
                        const float dist2 = sqi + sqB_s[lj] - 2.0f * g;
                        const float hinge = fmaxf(1.2f - dist2, 0.0f);
                        local += 0.3f + ((yi == yB_s[lj]) ? hinge : -hinge);
                    }
                }
            }
        }
    }

    #pragma unroll
    for (int o = 16; o; o >>= 1) local += __shfl_xor_sync(0xffffffffu, local, o);
    if (lane == 0) redr[wid] = local;
    __syncthreads();
    if (tid == 0) {
        float s = 0.f;
        #pragma unroll
        for (int i = 0; i < 8; i++) s += redr[i];
        atomicAdd(&g_acc, s);
    }
}

// ---------------------------------------------------------------------------
// Kernel 3: finalize
// ---------------------------------------------------------------------------
__global__ void finalize_kernel(float* out) {
    const double m = 1.0 / ((double)NB * (double)NB - (double)NB);
    out[0] = (float)((double)g_acc * m);
}

extern "C" void kernel_launch(void* const* d_in, const int* in_sizes, int n_in,
                              void* d_out, int out_size) {
    const float* x = (const float*)d_in[0];
    const long long* y = (const long long*)d_in[1];
    float* out = (float*)d_out;

    cudaFuncSetAttribute(gemm_loss, cudaFuncAttributeMaxDynamicSharedMemorySize, SMEM_TOTAL);

    prep_convert<<<NB / 8, 256>>>(x);
    gemm_loss<<<NPAIR, 256, SMEM_TOTAL>>>(y);
    finalize_kernel<<<1, 1>>>(out);
}

// round 9
// speedup vs baseline: 1.4216x; 1.1940x over previous
#include <cuda_runtime.h>
#include <cuda_bf16.h>
#include <cstdint>

#define NB 8192
#define ND 512
#define BM 128
#define BK 32
#define NK (ND / BK)                     // 16
#define NTILE (NB / BM)                  // 64
#define NPAIR (NTILE * (NTILE + 1) / 2)  // 2080
#define SST 40                           // bf16 elems per smem row
#define ROWB (SST * 2)                   // 80 bytes
#define NSTAGE 3
#define STAGE (BM * ROWB)                // 10240

#define OFF_A 0
#define OFF_B (NSTAGE * STAGE)                 // 30720
#define OFF_EPI (OFF_B + NSTAGE * STAGE)       // 61440
#define OFF_INVA (OFF_EPI)
#define OFF_SQA  (OFF_INVA + 512)
#define OFF_INVB (OFF_SQA + 512)
#define OFF_SQB  (OFF_INVB + 512)
#define OFF_YA   (OFF_SQB + 512)
#define OFF_YB   (OFF_YA + 1024)
#define OFF_RED  (OFF_YB + 1024)
#define SMEM_TOTAL (OFF_RED + 64)              // ~65.6 KB -> 2 CTAs/SM

__device__ float g_inv[NB];
__device__ float g_sq[NB];
__device__ float g_acc;
__device__ __nv_bfloat16 g_xbf[(size_t)NB * ND];

__device__ __forceinline__ uint32_t smem_to_u32(const void* p) {
    uint32_t a;
    asm("{ .reg .u64 t; cvta.to.shared.u64 t, %1; cvt.u32.u64 %0, t; }" : "=r"(a) : "l"(p));
    return a;
}
__device__ __forceinline__ void cp_async16(uint32_t saddr, const void* gaddr) {
    asm volatile("cp.async.cg.shared.global [%0], [%1], 16;" :: "r"(saddr), "l"(gaddr) : "memory");
}
__device__ __forceinline__ void ldmx4(uint32_t* r, uint32_t addr) {
    asm volatile("ldmatrix.sync.aligned.m8n8.x4.shared.b16 {%0,%1,%2,%3}, [%4];"
                 : "=r"(r[0]), "=r"(r[1]), "=r"(r[2]), "=r"(r[3]) : "r"(addr));
}
__device__ __forceinline__ void mma16816(float* c, const uint32_t* a, uint32_t b0, uint32_t b1) {
    asm volatile(
        "mma.sync.aligned.m16n8k16.row.col.f32.bf16.bf16.f32 "
        "{%0,%1,%2,%3}, {%4,%5,%6,%7}, {%8,%9}, {%0,%1,%2,%3};"
        : "+f"(c[0]), "+f"(c[1]), "+f"(c[2]), "+f"(c[3])
        : "r"(a[0]), "r"(a[1]), "r"(a[2]), "r"(a[3]), "r"(b0), "r"(b1));
}

// ---------------------------------------------------------------------------
// Kernel 1: fused norms + fp32->bf16 conversion. One warp per row.
// ---------------------------------------------------------------------------
__global__ __launch_bounds__(256) void prep_convert(const float* __restrict__ x) {
    int row = blockIdx.x * 8 + (threadIdx.x >> 5);
    int lane = threadIdx.x & 31;
    const float4* xr = (const float4*)(x + (size_t)row * ND) + lane * 4;
    float4 v[4];
    v[0] = xr[0]; v[1] = xr[1]; v[2] = xr[2]; v[3] = xr[3];

    float s = 0.f;
    #pragma unroll
    for (int i = 0; i < 4; i++)
        s += v[i].x * v[i].x + v[i].y * v[i].y + v[i].z * v[i].z + v[i].w * v[i].w;
    #pragma unroll
    for (int o = 16; o; o >>= 1) s += __shfl_xor_sync(0xffffffffu, s, o);

    float inv = 1.0f / sqrtf(s);

    float sq = 0.f;
    #pragma unroll
    for (int i = 0; i < 4; i++) {
        float a = v[i].x * inv, b = v[i].y * inv, c = v[i].z * inv, d = v[i].w * inv;
        sq += a * a + b * b + c * c + d * d;
    }
    #pragma unroll
    for (int o = 16; o; o >>= 1) sq += __shfl_xor_sync(0xffffffffu, sq, o);

    if (lane == 0) {
        g_inv[row] = inv;
        g_sq[row] = sq;
        if (row == 0) g_acc = 0.f;
    }

    uint32_t u[8];
    #pragma unroll
    for (int i = 0; i < 4; i++) {
        __nv_bfloat162 p0 = __floats2bfloat162_rn(v[i].x, v[i].y);
        __nv_bfloat162 p1 = __floats2bfloat162_rn(v[i].z, v[i].w);
        u[2 * i]     = *reinterpret_cast<uint32_t*>(&p0);
        u[2 * i + 1] = *reinterpret_cast<uint32_t*>(&p1);
    }
    uint4* dst = (uint4*)(g_xbf + (size_t)row * ND + lane * 16);
    dst[0] = make_uint4(u[0], u[1], u[2], u[3]);
    dst[1] = make_uint4(u[4], u[5], u[6], u[7]);
}

// ---------------------------------------------------------------------------
// Kernel 2: 128x128 CTA tile, 8 warps (4Mx2N), warp tile 32x64.
// 3-stage cp.async pipeline, FULLY UNROLLED k-loop (compile-time stage
// indices), ONE __syncthreads per k-iter. Fused loss epilogue.
// ---------------------------------------------------------------------------
__global__ __launch_bounds__(256, 2) void gemm_loss(const long long* __restrict__ y) {
    extern __shared__ char smem[];
    const uint32_t sb = smem_to_u32(smem);
    const int tid = threadIdx.x;
    const int lane = tid & 31;
    const int wid = tid >> 5;
    const int wm = wid & 3;     // 0..3  -> 32-row slab
    const int wn = wid >> 2;    // 0..1  -> 64-col slab

    // decode upper-triangle pair (bi, bj)
    int t = blockIdx.x, bi = 0;
    while (t >= NTILE - bi) { t -= NTILE - bi; bi++; }
    const int bj = bi + t;

    float* invA_s = (float*)(smem + OFF_INVA);
    float* sqA_s  = (float*)(smem + OFF_SQA);
    float* invB_s = (float*)(smem + OFF_INVB);
    float* sqB_s  = (float*)(smem + OFF_SQB);
    long long* yA_s = (long long*)(smem + OFF_YA);
    long long* yB_s = (long long*)(smem + OFF_YB);
    float* redr = (float*)(smem + OFF_RED);

    if (tid < BM) {
        const int gi = bi * BM + tid, gj = bj * BM + tid;
        invA_s[tid] = g_inv[gi]; sqA_s[tid] = g_sq[gi]; yA_s[tid] = y[gi];
        invB_s[tid] = g_inv[gj]; sqB_s[tid] = g_sq[gj]; yB_s[tid] = y[gj];
    }

    // global load mapping: each thread owns 32B of one A row and one B row
    const int lrow = tid >> 1;
    const int lc0 = (tid & 1) * 2;   // 16B-chunk index 0 or 2
    const __nv_bfloat16* gA = g_xbf + (size_t)(bi * BM + lrow) * ND + lc0 * 8;
    const __nv_bfloat16* gB = g_xbf + (size_t)(bj * BM + lrow) * ND + lc0 * 8;
    const uint32_t soff = (uint32_t)lrow * ROWB + lc0 * 16;

#define LOAD_STAGE(st, kk) do {                                               \
        const uint32_t _a = sb + OFF_A + (st) * STAGE + soff;                 \
        const uint32_t _b = sb + OFF_B + (st) * STAGE + soff;                 \
        const __nv_bfloat16* _ga = gA + (kk) * BK;                            \
        const __nv_bfloat16* _gb = gB + (kk) * BK;                            \
        cp_async16(_a,      _ga);                                             \
        cp_async16(_a + 16, _ga + 8);                                         \
        cp_async16(_b,      _gb);                                             \
        cp_async16(_b + 16, _gb + 8);                                         \
        asm volatile("cp.async.commit_group;" ::: "memory");                  \
    } while (0)

    // ldmatrix lane addressing (proven R5 mapping)
    const int lr = lane & 7, lg = lane >> 3;
    const uint32_t aoff = (uint32_t)(wm * 32 + lr + (lg & 1) * 8) * ROWB + (lg >> 1) * 16;
    const uint32_t boff = (uint32_t)(wn * 64 + lr + (lg >> 1) * 8) * ROWB + (lg & 1) * 16;

    float c[2][8][4];
    #pragma unroll
    for (int mt = 0; mt < 2; mt++)
        #pragma unroll
        for (int nt = 0; nt < 8; nt++)
            #pragma unroll
            for (int r = 0; r < 4; r++) c[mt][nt][r] = 0.f;

    LOAD_STAGE(0, 0);
    LOAD_STAGE(1, 1);
    LOAD_STAGE(2, 2);

    #pragma unroll
    for (int k = 0; k < NK; k++) {
        // wait until stage (k % 3)'s group has landed
        if (k < NK - 2)       asm volatile("cp.async.wait_group 2;" ::: "memory");
        else if (k == NK - 2) asm volatile("cp.async.wait_group 1;" ::: "memory");
        else                  asm volatile("cp.async.wait_group 0;" ::: "memory");
        __syncthreads();   // also fences iter k-1's compute on stage (k+3)%3

        if (k + 3 < NK) LOAD_STAGE((k + 3) % NSTAGE, k + 3);

        const uint32_t uA = sb + OFF_A + (k % NSTAGE) * STAGE;
        const uint32_t uB = sb + OFF_B + (k % NSTAGE) * STAGE;

        #pragma unroll
        for (int ks = 0; ks < 2; ks++) {
            uint32_t af[2][4], bf[4][4];
            #pragma unroll
            for (int mt = 0; mt < 2; mt++)
                ldmx4(af[mt], uA + aoff + mt * 16 * ROWB + ks * 32);
            #pragma unroll
            for (int p = 0; p < 4; p++)
                ldmx4(bf[p], uB + boff + p * 16 * ROWB + ks * 32);
            #pragma unroll
            for (int mt = 0; mt < 2; mt++)
                #pragma unroll
                for (int nt = 0; nt < 8; nt++)
                    mma16816(c[mt][nt], af[mt], bf[nt >> 1][(nt & 1) * 2],
                             bf[nt >> 1][(nt & 1) * 2 + 1]);
        }
    }

    // ---- fused loss epilogue on register fragments ----
    const int quad = lane >> 2;    // 0..7
    const int qt = lane & 3;       // 0..3
    float local = 0.f;

    #pragma unroll
    for (int mt = 0; mt < 2; mt++) {
        #pragma unroll
        for (int r2 = 0; r2 < 2; r2++) {
            const int li = wm * 32 + mt * 16 + quad + r2 * 8;
            const int gi = bi * BM + li;
            const float invi = invA_s[li], sqi = sqA_s[li];
            const long long yi = yA_s[li];
            #pragma unroll
            for (int nt = 0; nt < 8; nt++) {
                #pragma unroll
                for (int r1 = 0; r1 < 2; r1++) {
                    const int lj = wn * 64 + nt * 8 + 2 * qt + r1;
                    const int gj = bj * BM + lj;
                    if (gj >= gi) {
                        const float g = c[mt][nt][r2 * 2 + r1] * invi * invB_s[lj];
                        const float dist2 = sqi + sqB_s[lj] - 2.0f * g;
                        const float hinge = fmaxf(1.2f - dist2, 0.0f);
                        local += 0.3f + ((yi == yB_s[lj]) ? hinge : -hinge);
                    }
                }
            }
        }
    }

    #pragma unroll
    for (int o = 16; o; o >>= 1) local += __shfl_xor_sync(0xffffffffu, local, o);
    if (lane == 0) redr[wid] = local;
    __syncthreads();
    if (tid == 0) {
        float s = 0.f;
        #pragma unroll
        for (int i = 0; i < 8; i++) s += redr[i];
        atomicAdd(&g_acc, s);
    }
}

// ---------------------------------------------------------------------------
// Kernel 3: finalize
// ---------------------------------------------------------------------------
__global__ void finalize_kernel(float* out) {
    const double m = 1.0 / ((double)NB * (double)NB - (double)NB);
    out[0] = (float)((double)g_acc * m);
}

extern "C" void kernel_launch(void* const* d_in, const int* in_sizes, int n_in,
                              void* d_out, int out_size) {
    const float* x = (const float*)d_in[0];
    const long long* y = (const long long*)d_in[1];
    float* out = (float*)d_out;

    cudaFuncSetAttribute(gemm_loss, cudaFuncAttributeMaxDynamicSharedMemorySize, SMEM_TOTAL);

    prep_convert<<<NB / 8, 256>>>(x);
    gemm_loss<<<NPAIR, 256, SMEM_TOTAL>>>(y);
    finalize_kernel<<<1, 1>>>(out);
}